// round 17
// baseline (speedup 1.0000x reference)
#include <cuda_runtime.h>
#include <cstdint>

#define B_N 4
#define T_N 20000
#define E_N 2000
#define I_N 500
#define SUB 20
#define HID 10
#define COS 24
#define TNO 200

typedef unsigned long long ull;

// ---------------- scratch (static device globals; no allocation) ----------------
__device__ float  g_syn_ep[6][B_N * SUB * T_N];  // K-split partial E results
__device__ float  g_syn_ip[2][B_N * SUB * T_N];  // K-split partial I results
__device__ ull    g_Wpe[E_N * 10];               // packed sub-pair weights (C*exp(scale))
__device__ ull    g_Wpi[512 * 10];               // padded to 512 cols (500..511 zero)
__device__ ull    g_Kp[SUB * TNO * 10];          // conv taps: [s][d][p], p<5 E, p>=5 I
__device__ float  g_expW2[SUB * HID];
__device__ ull    g_biasP[SUB * 5];
__device__ float  g_sub_scratch[B_N * T_N * SUB];
__device__ float  g_Ce_scratch[SUB * E_N];
__device__ float  g_Ci_scratch[SUB * I_N];

// ---------------- f32x2 packed-math helpers (sm_103a) ----------------
__device__ __forceinline__ ull pack2(float x, float y) {
    ull r; asm("mov.b64 %0,{%1,%2};" : "=l"(r) : "f"(x), "f"(y)); return r;
}
__device__ __forceinline__ ull fma2(ull a, ull b, ull c) {
    ull d; asm("fma.rn.f32x2 %0,%1,%2,%3;" : "=l"(d) : "l"(a), "l"(b), "l"(c)); return d;
}
__device__ __forceinline__ void unpack2(ull v, float& x, float& y) {
    asm("mov.b64 {%0,%1},%2;" : "=f"(x), "=f"(y) : "l"(v));
}
__device__ __forceinline__ void cpa16(uint32_t smem, const void* gmem) {
    asm volatile("cp.async.cg.shared.global [%0], [%1], 16;" :: "r"(smem), "l"(gmem));
}

// ---------------- kernel 1: column softmax over subs + packed weight build ----------------
__global__ void softmax_kernel(const float* __restrict__ raw, const float* __restrict__ g,
                               const float* __restrict__ lsc, const int* __restrict__ testp,
                               int N, int isE, float* dout, int out_size)
{
    int e = blockIdx.x * blockDim.x + threadIdx.x;
    if (e >= N) return;
    int test = *testp;
    float sc = test ? 10000.f : 1000.f;
    float v[SUB];
    float m = -1e30f;
#pragma unroll
    for (int s = 0; s < SUB; s++) {
        float x = raw[s * N + e];
        if (!test) x += g[s * N + e];
        x *= sc;
        v[s] = x;
        m = fmaxf(m, x);
    }
    float sum = 0.f;
#pragma unroll
    for (int s = 0; s < SUB; s++) { v[s] = expf(v[s] - m); sum += v[s]; }
    float inv = 1.f / sum;
#pragma unroll
    for (int s = 0; s < SUB; s++) v[s] *= inv;

    float* cdst;
    if (out_size == 1730000) cdst = dout + (isE ? 1680000 : 1720000);
    else                     cdst = isE ? g_Ce_scratch : g_Ci_scratch;
#pragma unroll
    for (int s = 0; s < SUB; s++) cdst[s * N + e] = v[s];

    float ex = expf(lsc[e]);
    ull* wp = isE ? g_Wpe : g_Wpi;
#pragma unroll
    for (int p = 0; p < 10; p++)
        wp[e * 10 + p] = pack2(v[2 * p] * ex, v[2 * p + 1] * ex);
}

// ---------------- kernel 2: fold basis into combined 200-tap conv kernels ----------------
__device__ __forceinline__ float basisv(int k, int d) {
    const float PI = 3.14159265358979f;
    float raw = 6.f * logf((float)d + 1.f + 1e-7f);
    float phi = 1.57079632679f * (float)k;
    if (raw >= phi - PI && raw <= phi + PI) return 0.5f * cosf(raw - phi) + 0.5f;
    return 0.f;
}

__global__ void prep_kernel(const float* __restrict__ We, const float* __restrict__ Wi,
                            const float* __restrict__ W2, const float* __restrict__ b1)
{
    int i = blockIdx.x * blockDim.x + threadIdx.x;
    if (i < SUB * HID) g_expW2[i] = expf(W2[i]);
    if (i < SUB * 5)   g_biasP[i] = pack2(b1[2 * i], b1[2 * i + 1]);
    if (i >= 5000 && i < 5120) g_Wpi[i] = 0ull;   // zero I-pad cols 500..511
    if (i >= SUB * TNO * 10) return;
    int s = i / (TNO * 10);
    int r = i % (TNO * 10);
    int d = r / 10;
    int p = r % 10;
    const float* W = (p < 5) ? We : Wi;
    int pp = (p < 5) ? p : (p - 5);
    float k0 = 0.f, k1 = 0.f;
#pragma unroll
    for (int k = 0; k < COS; k++) {
        float bv = basisv(k, d);
        k0 += bv * W[(s * HID + 2 * pp) * COS + k];
        k1 += bv * W[(s * HID + 2 * pp + 1) * COS + k];
    }
    g_Kp[(s * TNO + d) * 10 + p] = pack2(k0, k1);
}

// ---------------- kernel 3: syn = S @ W^T  K-split (6 E + 2 I segs), chunk=16, M-tile=2 ----------------
// grid = (313, 8). chunk = 16 K-cols: stage = 256 rows x 64B + 160 ull W = 17.3 KB
// -> 6 CTAs/SM (was 5). E: 125 chunks, segs of 21/21/21/21/21/20. I: padded K=512, 2 segs x 16.
#define GROWS 256
#define NROW_TOT (B_N * T_N)

__global__ void __launch_bounds__(128, 6) gemm_kernel(const float* __restrict__ SE,
                                                      const float* __restrict__ SI)
{
    __shared__ __align__(16) float sS[2][GROWS * 16];
    __shared__ __align__(16) ull   sW[2][160];
    int seg = blockIdx.y;
    int isE = (seg < 6);
    const float* S;
    const ull* Wp;
    float* syn;
    int K, c0, c1;
    if (isE) {
        S = SE; K = E_N; Wp = g_Wpe; syn = g_syn_ep[seg];
        c0 = seg * 21; c1 = (seg == 5) ? 125 : (c0 + 21);
    } else {
        int s2 = seg - 6;
        S = SI; K = I_N; Wp = g_Wpi; syn = g_syn_ip[s2];
        c0 = s2 * 16; c1 = c0 + 16;
    }

    int tid = threadIdx.x;
    size_t rowBase = (size_t)blockIdx.x * GROWS;
    const size_t maxOffI = (size_t)NROW_TOT * I_N - 4;   // clamp for padded I cols

    // issue stage for absolute chunk c into buffer (c-c0)&1 (8 S-loads + <=1 W-load per thread)
    auto issue = [&](int c) {
        int buf = (c - c0) & 1;
        uint32_t sSb = (uint32_t)__cvta_generic_to_shared(&sS[buf][0]);
        uint32_t sWb = (uint32_t)__cvta_generic_to_shared(&sW[buf][0]);
#pragma unroll
        for (int k = 0; k < 8; k++) {
            int idx = tid + 128 * k;
            int row = idx >> 2, q = idx & 3;
            size_t rowg = rowBase + row;
            if (rowg > NROW_TOT - 1) rowg = NROW_TOT - 1;   // tail clamp (dup read, unstored)
            size_t off = rowg * (size_t)K + c * 16 + q * 4;
            if (!isE && off > maxOffI) off = maxOffI;       // padded cols: W=0, value unused
            cpa16(sSb + row * 64 + q * 16, S + off);
        }
        if (tid < 80)
            cpa16(sWb + tid * 16, Wp + c * 160 + tid * 2);
    };

    issue(c0);     asm volatile("cp.async.commit_group;");
    issue(c0 + 1); asm volatile("cp.async.commit_group;");

    ull acc0[10], acc1[10];
#pragma unroll
    for (int p = 0; p < 10; p++) { acc0[p] = 0ull; acc1[p] = 0ull; }

    for (int c = c0; c < c1; c++) {
        asm volatile("cp.async.wait_group 1;");
        __syncthreads();
        int buf = (c - c0) & 1;
        const float4* vr0 = reinterpret_cast<const float4*>(&sS[buf][tid * 16]);
        const float4* vr1 = reinterpret_cast<const float4*>(&sS[buf][(tid + 128) * 16]);
        const ull* wb = &sW[buf][0];
#pragma unroll
        for (int jq = 0; jq < 4; jq++) {
            float4 a4 = vr0[jq];
            float4 b4 = vr1[jq];
            float aa[4] = { a4.x, a4.y, a4.z, a4.w };
            float bb[4] = { b4.x, b4.y, b4.z, b4.w };
#pragma unroll
            for (int i = 0; i < 4; i++) {
                ull va = pack2(aa[i], aa[i]);
                ull vb = pack2(bb[i], bb[i]);
                const ulonglong2* wp2 =
                    reinterpret_cast<const ulonglong2*>(wb + (jq * 4 + i) * 10);
                ulonglong2 w0 = wp2[0], w1 = wp2[1], w2 = wp2[2], w3 = wp2[3], w4 = wp2[4];
                acc0[0] = fma2(va, w0.x, acc0[0]);  acc1[0] = fma2(vb, w0.x, acc1[0]);
                acc0[1] = fma2(va, w0.y, acc0[1]);  acc1[1] = fma2(vb, w0.y, acc1[1]);
                acc0[2] = fma2(va, w1.x, acc0[2]);  acc1[2] = fma2(vb, w1.x, acc1[2]);
                acc0[3] = fma2(va, w1.y, acc0[3]);  acc1[3] = fma2(vb, w1.y, acc1[3]);
                acc0[4] = fma2(va, w2.x, acc0[4]);  acc1[4] = fma2(vb, w2.x, acc1[4]);
                acc0[5] = fma2(va, w2.y, acc0[5]);  acc1[5] = fma2(vb, w2.y, acc1[5]);
                acc0[6] = fma2(va, w3.x, acc0[6]);  acc1[6] = fma2(vb, w3.x, acc1[6]);
                acc0[7] = fma2(va, w3.y, acc0[7]);  acc1[7] = fma2(vb, w3.y, acc1[7]);
                acc0[8] = fma2(va, w4.x, acc0[8]);  acc1[8] = fma2(vb, w4.x, acc1[8]);
                acc0[9] = fma2(va, w4.y, acc0[9]);  acc1[9] = fma2(vb, w4.y, acc1[9]);
            }
        }
        __syncthreads();
        if (c + 2 < c1) issue(c + 2);
        asm volatile("cp.async.commit_group;");
    }

    // epilogue: store both rows (guard tail)
#pragma unroll
    for (int half = 0; half < 2; half++) {
        size_t r = rowBase + tid + half * 128;
        if (r >= NROW_TOT) break;
        ull* accp = half ? acc1 : acc0;
        int b = (int)(r / T_N);
        int t = (int)(r % T_N);
        float* outp = syn + (size_t)b * SUB * T_N + t;
#pragma unroll
        for (int p = 0; p < 10; p++) {
            float h0, h1; unpack2(accp[p], h0, h1);
            outp[(size_t)(2 * p) * T_N] = h0;
            outp[(size_t)(2 * p + 1) * T_N] = h1;
        }
    }
}

// ---------------- kernel 4: 200-tap causal conv (e+i) + tanh + layer2 reduce ----------------
// Block: 256 threads, tile of 1024 t (4 per thread, strided by 256).
// syn assembled from K-split partials (6 E + 2 I) during load; values pre-packed (v,v).
#define CTILE 1024
#define CHALO 199
#define CSME (CTILE + CHALO)   // 1223

__global__ void __launch_bounds__(256, 3) conv_kernel(float* __restrict__ dout, int out_size)
{
    __shared__ __align__(16) ull sE[CSME];
    __shared__ __align__(16) ull sI[CSME];
    __shared__ __align__(16) ull sK[TNO * 10];
    int tid = threadIdx.x;
    int s = blockIdx.y, b = blockIdx.z;
    int t0 = blockIdx.x * CTILE;

    size_t chan = (size_t)(b * SUB + s) * T_N;
    for (int l = tid; l < CSME; l += 256) {
        int t = t0 - CHALO + l;
        float ve = 0.f, vi = 0.f;
        if (t >= 0 && t < T_N) {
            ve = g_syn_ep[0][chan + t] + g_syn_ep[1][chan + t] + g_syn_ep[2][chan + t]
               + g_syn_ep[3][chan + t] + g_syn_ep[4][chan + t] + g_syn_ep[5][chan + t];
            vi = g_syn_ip[0][chan + t] + g_syn_ip[1][chan + t];
        }
        sE[l] = pack2(ve, ve);
        sI[l] = pack2(vi, vi);
    }
    const ull* Kg = g_Kp + (size_t)s * (TNO * 10);
    for (int l = tid; l < TNO * 10; l += 256) sK[l] = Kg[l];
    __syncthreads();

    ull acc[4][5];
#pragma unroll
    for (int j = 0; j < 4; j++)
#pragma unroll
        for (int p = 0; p < 5; p++) acc[j][p] = g_biasP[s * 5 + p];

    int l0 = CHALO + tid;   // entry for (j=0, d=0); t_j entry = l0 + j*256 - d

#pragma unroll 2
    for (int d = 0; d < TNO; d++) {
        const ulonglong2* kp = reinterpret_cast<const ulonglong2*>(&sK[d * 10]);
        ulonglong2 k01 = kp[0], k23 = kp[1], k45 = kp[2], k67 = kp[3], k89 = kp[4];
#pragma unroll
        for (int j = 0; j < 4; j++) {
            int li = l0 + j * 256 - d;
            ull ve = sE[li];
            ull vi = sI[li];
            acc[j][0] = fma2(ve, k01.x, acc[j][0]);
            acc[j][1] = fma2(ve, k01.y, acc[j][1]);
            acc[j][2] = fma2(ve, k23.x, acc[j][2]);
            acc[j][3] = fma2(ve, k23.y, acc[j][3]);
            acc[j][4] = fma2(ve, k45.x, acc[j][4]);
            acc[j][0] = fma2(vi, k45.y, acc[j][0]);
            acc[j][1] = fma2(vi, k67.x, acc[j][1]);
            acc[j][2] = fma2(vi, k67.y, acc[j][2]);
            acc[j][3] = fma2(vi, k89.x, acc[j][3]);
            acc[j][4] = fma2(vi, k89.y, acc[j][4]);
        }
    }

    float* subdst = (out_size == 1730000) ? (dout + 80000) : g_sub_scratch;
    float ew[10];
#pragma unroll
    for (int h = 0; h < 10; h++) ew[h] = g_expW2[s * 10 + h];

#pragma unroll
    for (int j = 0; j < 4; j++) {
        int t = t0 + tid + j * 256;
        if (t >= T_N) continue;
        float res = 0.f;
#pragma unroll
        for (int p = 0; p < 5; p++) {
            float h0, h1; unpack2(acc[j][p], h0, h1);
            res += tanhf(h0) * ew[2 * p] + tanhf(h1) * ew[2 * p + 1];
        }
        subdst[((size_t)b * T_N + t) * SUB + s] = res;
    }
}

// ---------------- kernel 5: final[b,t] = sum_s sub_out + V_o ----------------
__global__ void final_kernel(float* dout, int out_size, const float* __restrict__ Vo)
{
    int idx = blockIdx.x * blockDim.x + threadIdx.x;
    if (idx >= B_N * T_N) return;
    const float* src = (out_size == 1730000) ? (dout + 80000) : g_sub_scratch;
    const float4* p = reinterpret_cast<const float4*>(src + (size_t)idx * SUB);
    float sum = 0.f;
#pragma unroll
    for (int i = 0; i < 5; i++) {
        float4 v = p[i];
        sum += v.x + v.y + v.z + v.w;
    }
    dout[idx] = sum + Vo[0];
}

// ---------------- launch ----------------
extern "C" void kernel_launch(void* const* d_in, const int* in_sizes, int n_in,
                              void* d_out, int out_size)
{
    const float* S_e     = (const float*)d_in[0];
    const float* S_i     = (const float*)d_in[1];
    const int*   testp   = (const int*)  d_in[3];
    const float* g_e     = (const float*)d_in[4];
    const float* g_i     = (const float*)d_in[5];
    const float* E_scale = (const float*)d_in[6];
    const float* I_scale = (const float*)d_in[7];
    const float* We      = (const float*)d_in[8];
    const float* Wi      = (const float*)d_in[9];
    const float* W2      = (const float*)d_in[10];
    const float* b1      = (const float*)d_in[11];
    const float* Ce      = (const float*)d_in[12];
    const float* Ci      = (const float*)d_in[13];
    const float* Vo      = (const float*)d_in[14];
    float* out = (float*)d_out;

    softmax_kernel<<<(E_N + 127) / 128, 128>>>(Ce, g_e, E_scale, testp, E_N, 1, out, out_size);
    softmax_kernel<<<(I_N + 127) / 128, 128>>>(Ci, g_i, I_scale, testp, I_N, 0, out, out_size);
    prep_kernel<<<(SUB * TNO * 10 + 255) / 256, 256>>>(We, Wi, W2, b1);
    dim3 gg((NROW_TOT + GROWS - 1) / GROWS, 8);
    gemm_kernel<<<gg, 128>>>(S_e, S_i);
    dim3 cg((T_N + CTILE - 1) / CTILE, SUB, B_N);
    conv_kernel<<<cg, 256>>>(out, out_size);
    final_kernel<<<(B_N * T_N + 255) / 256, 256>>>(out, out_size, Vo);
}